// round 15
// baseline (speedup 1.0000x reference)
#include <cuda_runtime.h>
#include <cuda_bf16.h>

#define INPUT   128
#define HIDDEN  1024
#define OUTPUT  128
#define BATCH   256
#define TSTEPS  512

// ---------------------------- device globals -------------------------------
__device__ float g_beff[HIDDEN];
__device__ float g_b1[HIDDEN];
// bf16 split planes of h_t for every t: [t][hh=0/hl=1][m][k]
__device__ __align__(16) __nv_bfloat16 g_Hs[TSTEPS][2][BATCH][HIDDEN];
// bf16 split of W_eff, transposed (n-major): [Wh=0/Wl=1][n][k]
__device__ __align__(16) __nv_bfloat16 g_BT[2][HIDDEN][HIDDEN];
// bf16 split of W_h2o, transposed (n-major): [Wh=0/Wl=1][n][k]
__device__ __align__(16) __nv_bfloat16 g_BTo[2][OUTPUT][HIDDEN];

// ---------------------------- PTX helpers ----------------------------------
__device__ __forceinline__ unsigned smem_u32(const void* p) {
    unsigned a;
    asm("{ .reg .u64 t; cvta.to.shared.u64 t, %1; cvt.u32.u64 %0, t; }"
        : "=r"(a) : "l"(p));
    return a;
}
__device__ __forceinline__ void cp16(unsigned s, const void* g) {
    asm volatile("cp.async.cg.shared.global [%0], [%1], 16;"
                 :: "r"(s), "l"(g) : "memory");
}
__device__ __forceinline__ void cp_commit() {
    asm volatile("cp.async.commit_group;" ::: "memory");
}
__device__ __forceinline__ void ldm4(unsigned* r, unsigned addr) {
    asm volatile("ldmatrix.sync.aligned.m8n8.x4.shared.b16 {%0,%1,%2,%3}, [%4];"
                 : "=r"(r[0]), "=r"(r[1]), "=r"(r[2]), "=r"(r[3]) : "r"(addr));
}
__device__ __forceinline__ void mma16816(float* d, const unsigned* a,
                                         const unsigned* b) {
    asm volatile(
        "mma.sync.aligned.m16n8k16.row.col.f32.bf16.bf16.f32 "
        "{%0,%1,%2,%3}, {%4,%5,%6,%7}, {%8,%9}, {%0,%1,%2,%3};"
        : "+f"(d[0]), "+f"(d[1]), "+f"(d[2]), "+f"(d[3])
        : "r"(a[0]), "r"(a[1]), "r"(a[2]), "r"(a[3]), "r"(b[0]), "r"(b[1]));
}

// ===========================================================================
// Fused launch: CTAs [0, nStep) compute h_t = tanh(h_{t-1} @ W_eff + b_eff);
// CTAs [nStep, nStep+16) compute out[t-1] = h_{t-1} @ W_h2o + b_h2o.
// Both modes: CTA tile 32x64, warp tile 16x16 (8 warps 2m x 4n), K=1024,
// 3-pass bf16 split (hh@Wh + hl@Wh + hh@Wl; hl@Wl dropped ~2^-18).
// Pipeline: BK=32 stages, 5 slots, 4 in flight, one sync/stage.
// PDL: B (weight) prefetch for stages 0-3 issues BEFORE
// cudaGridDependencySynchronize(); A (h_{t-1}) loads after. Trigger fires
// after the mainloop so the next step's CTAs launch onto retiring SMs.
// smem 75KB: AH/AL[5][32][40], BH/BL[5][64][40] bf16.
// ===========================================================================
#define S_APAD   40
#define S_ASLOT  (32 * S_APAD)              // 1280 elems
#define S_BSLOT  (64 * S_APAD)              // 2560 elems
#define S_AH     0
#define S_AL     (5 * S_ASLOT)              // 6400
#define S_BH     (10 * S_ASLOT)             // 12800
#define S_BL     (S_BH + 5 * S_BSLOT)       // 25600
#define S_TOT_E  (S_BH + 10 * S_BSLOT)      // 38400 elems = 76800 B
#define S_NST    32                          // k32 stages

__global__ void __launch_bounds__(256, 1)
rnn_fused(int t, int nStep, const float* __restrict__ bh2o,
          float* __restrict__ out) {
    extern __shared__ __align__(16) __nv_bfloat16 dyn[];

    const int tid = threadIdx.x, wid = tid >> 5, l = tid & 31;
    const bool stepMode = (int)blockIdx.x < nStep;
    const int bx = stepMode ? blockIdx.x : blockIdx.x - nStep;

    int nBase, mBase;
    const __nv_bfloat16 *gBh, *gBl;
    if (stepMode) {
        nBase = (bx & 15) * 64;  mBase = (bx >> 4) * 32;
        gBh = &g_BT[0][nBase][0];  gBl = &g_BT[1][nBase][0];
    } else {
        nBase = (bx & 1) * 64;   mBase = (bx >> 1) * 32;
        gBh = &g_BTo[0][nBase][0]; gBl = &g_BTo[1][nBase][0];
    }
    const __nv_bfloat16* gAh = &g_Hs[t - 1][0][mBase][0];
    const __nv_bfloat16* gAl = &g_Hs[t - 1][1][mBase][0];

    auto load_B = [&](int slot, int st) {
        const int k0 = st * 32;
#pragma unroll
        for (int i = 0; i < 2; ++i) {   // B: 2 parts x 64 rows x 4 segs = 512
            int c = tid + i * 256;
            int part = c >> 8, r = (c & 255) >> 2, s = (c & 3) * 8;
            __nv_bfloat16* d = dyn + (part ? S_BL : S_BH) + slot * S_BSLOT
                               + r * S_APAD + s;
            cp16(smem_u32(d), (part ? gBl : gBh) + r * HIDDEN + k0 + s);
        }
    };
    auto load_A = [&](int slot, int st) {
        const int k0 = st * 32;
        int c = tid;                    // A: 2 parts x 32 rows x 4 segs = 256
        int part = c >> 7, r = (c & 127) >> 2, s = (c & 3) * 8;
        __nv_bfloat16* d = dyn + (part ? S_AL : S_AH) + slot * S_ASLOT
                           + r * S_APAD + s;
        cp16(smem_u32(d), (part ? gAl : gAh) + r * HIDDEN + k0 + s);
    };

    // ---- PDL prologue: weight prefetch does NOT depend on h_{t-1} ----
    load_B(0, 0);
    load_B(1, 1);
    load_B(2, 2);
    load_B(3, 3);

    cudaGridDependencySynchronize();    // wait for step t-1 completion

    load_A(0, 0); cp_commit();          // group0 = B(0..3) + A(0)
    load_A(1, 1); cp_commit();
    load_A(2, 2); cp_commit();
    load_A(3, 3); cp_commit();

    // ldmatrix lane offsets (bytes within a slot)
    const int rowA = ((wid >> 2) << 4) + (l & 15);
    const unsigned offA = (unsigned)(rowA * S_APAD + ((l >> 4) << 3)) * 2;
    const int rowB = ((wid & 3) << 4) + (l & 7) + ((l >> 4) << 3);
    const unsigned offB = (unsigned)(rowB * S_APAD + (((l >> 3) & 1) << 3)) * 2;

    const unsigned uAh = smem_u32(dyn + S_AH) + offA;
    const unsigned uAl = smem_u32(dyn + S_AL) + offA;
    const unsigned uBh = smem_u32(dyn + S_BH) + offB;
    const unsigned uBl = smem_u32(dyn + S_BL) + offB;

    float acc0[4] = {0.f, 0.f, 0.f, 0.f};
    float acc1[4] = {0.f, 0.f, 0.f, 0.f};

    for (int st = 0; st < S_NST; ++st) {
        asm volatile("cp.async.wait_group 3;" ::: "memory");
        __syncthreads();                  // stage st ready; slot st-1 free
        if (st + 4 < S_NST) { load_B((st + 4) % 5, st + 4); load_A((st + 4) % 5, st + 4); }
        cp_commit();

        const int slot = st % 5;
        const unsigned aH = uAh + (unsigned)(slot * S_ASLOT) * 2;
        const unsigned aL = uAl + (unsigned)(slot * S_ASLOT) * 2;
        const unsigned bH = uBh + (unsigned)(slot * S_BSLOT) * 2;
        const unsigned bL = uBl + (unsigned)(slot * S_BSLOT) * 2;

#pragma unroll
        for (int kj = 0; kj < 2; ++kj) {  // 2 x k16 per stage
            unsigned Ah[4], Al[4], Bh[4], Bl[4];
            ldm4(Ah, aH + kj * 32);
            ldm4(Al, aL + kj * 32);
            ldm4(Bh, bH + kj * 32);
            ldm4(Bl, bL + kj * 32);
            mma16816(acc0, Ah, Bh);
            mma16816(acc1, Ah, Bh + 2);
            mma16816(acc0, Al, Bh);
            mma16816(acc1, Al, Bh + 2);
            mma16816(acc0, Ah, Bl);
            mma16816(acc1, Ah, Bl + 2);
        }
    }
    asm volatile("cp.async.wait_group 0;" ::: "memory");

    // allow step t+1 to begin scheduling while we run the epilogue
    cudaTriggerProgrammaticLaunchCompletion();

    // ---- epilogues ----
    const int g = l >> 2, tq = l & 3;
    const int m0 = (wid >> 2) << 4;
    const int n0 = (wid & 3) << 4;

    if (stepMode) {
        // bias + tanh; write bf16 split planes for step t
#pragma unroll
        for (int half = 0; half < 2; ++half) {
            const int m = mBase + m0 + g + half * 8;
#pragma unroll
            for (int j = 0; j < 2; ++j) {
                const float* acc = j ? acc1 : acc0;
                const int n = nBase + n0 + j * 8 + 2 * tq;
                float v0 = tanhf(acc[2 * half]     + g_beff[n]);
                float v1 = tanhf(acc[2 * half + 1] + g_beff[n + 1]);
                __nv_bfloat16 h0 = __float2bfloat16(v0);
                __nv_bfloat16 h1 = __float2bfloat16(v1);
                __nv_bfloat162 hh; hh.x = h0; hh.y = h1;
                __nv_bfloat162 hl;
                hl.x = __float2bfloat16(v0 - __bfloat162float(h0));
                hl.y = __float2bfloat16(v1 - __bfloat162float(h1));
                *(__nv_bfloat162*)&g_Hs[t][0][m][n] = hh;
                *(__nv_bfloat162*)&g_Hs[t][1][m][n] = hl;
            }
        }
    } else {
        // out[t-1] rows (t-1)*256 + m; bias + fp32 store
#pragma unroll
        for (int half = 0; half < 2; ++half) {
            const int m = mBase + m0 + g + half * 8;
            float* rowp = out + ((size_t)(t - 1) * 256 + m) * OUTPUT;
#pragma unroll
            for (int j = 0; j < 2; ++j) {
                const float* acc = j ? acc1 : acc0;
                const int n = nBase + n0 + j * 8 + 2 * tq;
                *(float2*)&rowp[n] =
                    make_float2(acc[2 * half]     + bh2o[n],
                                acc[2 * half + 1] + bh2o[n + 1]);
            }
        }
    }
}

// ===========================================================================
// fp32 FFMA2 GEMM for rnn_first (K=128): writes bf16 split planes directly.
// ===========================================================================
__device__ __forceinline__ unsigned long long pack2(float lo, float hi) {
    unsigned long long r;
    asm("mov.b64 %0, {%1, %2};" : "=l"(r) : "f"(lo), "f"(hi));
    return r;
}
__device__ __forceinline__ void unpack2(unsigned long long v, float& lo, float& hi) {
    asm("mov.b64 {%0, %1}, %2;" : "=f"(lo), "=f"(hi) : "l"(v));
}
__device__ __forceinline__ void ffma2(unsigned long long& d,
                                      unsigned long long a, unsigned long long b) {
    asm("fma.rn.f32x2 %0, %1, %2, %0;" : "+l"(d) : "l"(a), "l"(b));
}

__global__ void rnn_first(const float* __restrict__ x0,
                          const float* __restrict__ Wi2h) {
    __shared__ unsigned long long Asd[2][16][34];
    __shared__ float Bs[2][16][68];

    const int tid = threadIdx.x;
    const int tx = tid & 15, ty = tid >> 4;
    const int rowBase = blockIdx.y * 32;
    const int colBase = blockIdx.x * 64;
    const int am = tid >> 3, ak = (tid & 7) * 2;
    const int bk = tid >> 4, bn = (tid & 15) * 4;

    const float* Aptr = &x0[(size_t)(rowBase + am) * INPUT + ak];
    const float* Bptr = &Wi2h[(size_t)bk * HIDDEN + colBase + bn];

    unsigned long long acc[2][2];
    acc[0][0] = acc[0][1] = acc[1][0] = acc[1][1] = 0ull;

    float2 rA = *(const float2*)Aptr;
    float4 rB = *(const float4*)Bptr;

    const int nT = INPUT >> 4;
    for (int tt = 0; tt < nT; ++tt) {
        const int buf = tt & 1;
        Asd[buf][ak][am]     = pack2(rA.x, rA.x);
        Asd[buf][ak + 1][am] = pack2(rA.y, rA.y);
        *(float4*)&Bs[buf][bk][bn] = rB;
        __syncthreads();
        if (tt + 1 < nT) {
            rA = *(const float2*)(Aptr + (tt + 1) * 16);
            rB = *(const float4*)(Bptr + (size_t)(tt + 1) * 16 * HIDDEN);
        }
#pragma unroll
        for (int kk = 0; kk < 16; ++kk) {
            ulonglong2 ap = *(const ulonglong2*)&Asd[buf][kk][2 * ty];
            ulonglong2 bp = *(const ulonglong2*)&Bs[buf][kk][4 * tx];
            ffma2(acc[0][0], ap.x, bp.x);
            ffma2(acc[0][1], ap.x, bp.y);
            ffma2(acc[1][0], ap.y, bp.x);
            ffma2(acc[1][1], ap.y, bp.y);
        }
    }

    float4 bv = *(const float4*)&g_b1[colBase + 4 * tx];
    float o[2][4];
#pragma unroll
    for (int r = 0; r < 2; ++r) {
        unpack2(acc[r][0], o[r][0], o[r][1]);
        unpack2(acc[r][1], o[r][2], o[r][3]);
        o[r][0] += bv.x; o[r][1] += bv.y; o[r][2] += bv.z; o[r][3] += bv.w;
        const int m = rowBase + 2 * ty + r;
        const int n = colBase + 4 * tx;
#pragma unroll
        for (int c = 0; c < 4; ++c) {
            float v = tanhf(o[r][c]);
            __nv_bfloat16 h = __float2bfloat16(v);
            g_Hs[1][0][m][n + c] = h;
            g_Hs[1][1][m][n + c] = __float2bfloat16(v - __bfloat162float(h));
        }
    }
}

// ---------------------------- prep kernels ---------------------------------
__global__ void prep_weff(const float* __restrict__ Wh2h,
                          const float* __restrict__ Wh2o,
                          const float* __restrict__ Wi2h) {
    int idx = blockIdx.x * blockDim.x + threadIdx.x;
    int k = idx >> 10, j = idx & 1023;
    float s = Wh2h[idx];
    const float* wo = &Wh2o[k * OUTPUT];
#pragma unroll 8
    for (int i = 0; i < OUTPUT; ++i)
        s += wo[i] * Wi2h[i * HIDDEN + j];
    __nv_bfloat16 wh = __float2bfloat16(s);
    g_BT[0][j][k] = wh;
    g_BT[1][j][k] = __float2bfloat16(s - __bfloat162float(wh));
}

__global__ void prep_bo(const float* __restrict__ Wh2o) {
    int idx = blockIdx.x * blockDim.x + threadIdx.x;   // HIDDEN*OUTPUT
    int k = idx >> 7, n = idx & 127;
    float w = Wh2o[k * OUTPUT + n];
    __nv_bfloat16 wh = __float2bfloat16(w);
    g_BTo[0][n][k] = wh;
    g_BTo[1][n][k] = __float2bfloat16(w - __bfloat162float(wh));
}

__global__ void prep_bias(const float* __restrict__ bi2h,
                          const float* __restrict__ bh2h,
                          const float* __restrict__ bh2o,
                          const float* __restrict__ Wi2h) {
    int j = blockIdx.x * blockDim.x + threadIdx.x;
    if (j >= HIDDEN) return;
    float base = bi2h[j] + bh2h[j];
    g_b1[j] = base;
    float s = base;
#pragma unroll 8
    for (int i = 0; i < OUTPUT; ++i)
        s += bh2o[i] * Wi2h[i * HIDDEN + j];
    g_beff[j] = s;
}

// ---------------------------- launcher -------------------------------------
extern "C" void kernel_launch(void* const* d_in, const int* in_sizes, int n_in,
                              void* d_out, int out_size) {
    const float* x0   = (const float*)d_in[0];
    const float* Wi2h = (const float*)d_in[1];
    const float* bi2h = (const float*)d_in[2];
    const float* Wh2h = (const float*)d_in[3];
    const float* bh2h = (const float*)d_in[4];
    const float* Wh2o = (const float*)d_in[5];
    const float* bh2o = (const float*)d_in[6];
    float* out = (float*)d_out;

    cudaFuncSetAttribute(rnn_fused,
                         cudaFuncAttributeMaxDynamicSharedMemorySize,
                         S_TOT_E * 2);

    prep_weff<<<(HIDDEN * HIDDEN) / 256, 256>>>(Wh2h, Wh2o, Wi2h);
    prep_bo<<<(HIDDEN * OUTPUT) / 256, 256>>>(Wh2o);
    prep_bias<<<(HIDDEN + 255) / 256, 256>>>(bi2h, bh2h, bh2o, Wi2h);
    cudaMemcpyAsync(out, x0, BATCH * OUTPUT * sizeof(float),
                    cudaMemcpyDeviceToDevice, 0);

    rnn_first<<<dim3(HIDDEN / 64, BATCH / 32), 256>>>(x0, Wi2h);

    // steps 2..511 with PDL: weight prefetch overlaps previous step's tail
    cudaLaunchAttribute attrs[1];
    attrs[0].id = cudaLaunchAttributeProgrammaticStreamSerialization;
    attrs[0].val.programmaticStreamSerializationAllowed = 1;

    cudaLaunchConfig_t cfg = {};
    cfg.blockDim = dim3(256, 1, 1);
    cfg.dynamicSmemBytes = S_TOT_E * 2;
    cfg.attrs = attrs;
    cfg.numAttrs = 1;

    for (int t = 2; t < TSTEPS; ++t) {
        cfg.gridDim = dim3(144, 1, 1);
        cudaLaunchKernelEx(&cfg, rnn_fused, t, 128, bh2o, out);
    }
    // final: out[511] only (16 CTAs, no step work)
    cfg.gridDim = dim3(16, 1, 1);
    cudaLaunchKernelEx(&cfg, rnn_fused, (int)TSTEPS, 0, bh2o, out);
}

// round 16
// speedup vs baseline: 1.1687x; 1.1687x over previous
#include <cuda_runtime.h>
#include <cuda_bf16.h>

#define INPUT   128
#define HIDDEN  1024
#define OUTPUT  128
#define BATCH   256
#define TSTEPS  512

// ---------------------------- device globals -------------------------------
__device__ float g_beff[HIDDEN];
__device__ float g_b1[HIDDEN];
// Tiled bf16 split planes of h_t: [t][mtile][stage][hh/hl][row 0..31][col 0..39]
// (stage = k/32; 40-col padded so a bulk-copied stage block is ldmatrix-ready)
__device__ __align__(16) __nv_bfloat16 g_Hst[TSTEPS][8][32][2][32][40];
// Tiled bf16 split of W_eff^T: [ntile][stage][Wh/Wl][row 0..63][col 0..39]
__device__ __align__(16) __nv_bfloat16 g_BTt[16][32][2][64][40];
// Tiled bf16 split of W_h2o^T: [ntile 0..1][stage][Wh/Wl][row 0..63][col 0..39]
__device__ __align__(16) __nv_bfloat16 g_BTot[2][32][2][64][40];

// ---------------------------- PTX helpers ----------------------------------
__device__ __forceinline__ unsigned smem_u32(const void* p) {
    unsigned a;
    asm("{ .reg .u64 t; cvta.to.shared.u64 t, %1; cvt.u32.u64 %0, t; }"
        : "=r"(a) : "l"(p));
    return a;
}
__device__ __forceinline__ void ldm4(unsigned* r, unsigned addr) {
    asm volatile("ldmatrix.sync.aligned.m8n8.x4.shared.b16 {%0,%1,%2,%3}, [%4];"
                 : "=r"(r[0]), "=r"(r[1]), "=r"(r[2]), "=r"(r[3]) : "r"(addr));
}
__device__ __forceinline__ void mma16816(float* d, const unsigned* a,
                                         const unsigned* b) {
    asm volatile(
        "mma.sync.aligned.m16n8k16.row.col.f32.bf16.bf16.f32 "
        "{%0,%1,%2,%3}, {%4,%5,%6,%7}, {%8,%9}, {%0,%1,%2,%3};"
        : "+f"(d[0]), "+f"(d[1]), "+f"(d[2]), "+f"(d[3])
        : "r"(a[0]), "r"(a[1]), "r"(a[2]), "r"(a[3]), "r"(b[0]), "r"(b[1]));
}
__device__ __forceinline__ void mbar_init(unsigned mbar, unsigned cnt) {
    asm volatile("mbarrier.init.shared.b64 [%0], %1;"
                 :: "r"(mbar), "r"(cnt) : "memory");
}
__device__ __forceinline__ void mbar_expect_tx(unsigned mbar, unsigned bytes) {
    asm volatile("mbarrier.arrive.expect_tx.shared.b64 _, [%0], %1;"
                 :: "r"(mbar), "r"(bytes) : "memory");
}
__device__ __forceinline__ void mbar_wait(unsigned mbar, unsigned parity) {
    asm volatile(
        "{\n\t.reg .pred P1;\n"
        "W%=:\n\t"
        "mbarrier.try_wait.parity.acquire.cta.shared::cta.b64 P1, [%0], %1, 0x989680;\n\t"
        "@P1 bra.uni D%=;\n\t"
        "bra.uni W%=;\n"
        "D%=:\n\t}"
        :: "r"(mbar), "r"(parity) : "memory");
}
__device__ __forceinline__ void bulk_g2s(unsigned dst, const void* src,
                                         unsigned bytes, unsigned mbar) {
    asm volatile(
        "cp.async.bulk.shared::cta.global.mbarrier::complete_tx::bytes "
        "[%0], [%1], %2, [%3];"
        :: "r"(dst), "l"(src), "r"(bytes), "r"(mbar) : "memory");
}

// ===========================================================================
// Fused launch: CTAs [0, nStep) compute h_t = tanh(h_{t-1} @ W_eff + b_eff);
// CTAs [nStep, nStep+16) compute out[t-1] = h_{t-1} @ W_h2o + b_h2o.
// CTA tile 32x64, warp tile 16x16 (8 warps 2m x 4n), K=1024, 3-pass bf16
// split (hh@Wh + hl@Wh + hh@Wl; hl@Wl dropped ~2^-18).
// Pipeline: BK=32 stages; per stage TWO cp.async.bulk (A 5120B + B 10240B)
// into one of 5 smem slots, mbarrier complete_tx, 4 stages in flight,
// one __syncthreads per stage (slot-reuse invariant).
// smem: 5 slots x 15360B = 76800B dynamic (+ 5 mbarriers static).
// ===========================================================================
#define APAD      40
#define A_BYTES   5120                  // 2 x 32 x 40 x 2
#define B_BYTES   10240                 // 2 x 64 x 40 x 2
#define SLOT_B    (A_BYTES + B_BYTES)   // 15360
#define NSLOT     5
#define SM_BYTES  (NSLOT * SLOT_B)      // 76800
#define NST       32

__global__ void __launch_bounds__(256, 1)
rnn_fused(int t, int nStep, const float* __restrict__ bh2o,
          float* __restrict__ out) {
    extern __shared__ __align__(128) __nv_bfloat16 dyn[];
    __shared__ __align__(8) unsigned long long mbarStore[NSLOT];

    const int tid = threadIdx.x, wid = tid >> 5, l = tid & 31;
    const bool stepMode = (int)blockIdx.x < nStep;
    const int bx = stepMode ? blockIdx.x : blockIdx.x - nStep;

    int nBase, mtile;
    const __nv_bfloat16* gB;
    if (stepMode) {
        nBase = (bx & 15) * 64;  mtile = bx >> 4;
        gB = &g_BTt[bx & 15][0][0][0][0];
    } else {
        nBase = (bx & 1) * 64;   mtile = bx >> 1;
        gB = &g_BTot[bx & 1][0][0][0][0];
    }
    const __nv_bfloat16* gA = &g_Hst[t - 1][mtile][0][0][0][0];

    const unsigned dynBase = smem_u32(dyn);
    const unsigned mbar0 = smem_u32(&mbarStore[0]);

    if (tid == 0) {
#pragma unroll
        for (int s = 0; s < NSLOT; ++s) mbar_init(mbar0 + s * 8, 1);
    }
    __syncthreads();

    auto issue = [&](int slot, int st) {
        if (tid == 0) {
            const unsigned mb = mbar0 + slot * 8;
            mbar_expect_tx(mb, SLOT_B);
            bulk_g2s(dynBase + slot * SLOT_B, gA + st * (A_BYTES / 2),
                     A_BYTES, mb);
            bulk_g2s(dynBase + slot * SLOT_B + A_BYTES,
                     gB + st * (B_BYTES / 2), B_BYTES, mb);
        }
    };

    issue(0, 0); issue(1, 1); issue(2, 2); issue(3, 3);

    // ldmatrix lane offsets (bytes within a slot)
    const int rowA = ((wid >> 2) << 4) + (l & 15);
    const unsigned offA = (unsigned)(rowA * APAD + ((l >> 4) << 3)) * 2;
    const int rowB = ((wid & 3) << 4) + (l & 7) + ((l >> 4) << 3);
    const unsigned offB = (unsigned)(rowB * APAD + (((l >> 3) & 1) << 3)) * 2;

    float acc0[4] = {0.f, 0.f, 0.f, 0.f};
    float acc1[4] = {0.f, 0.f, 0.f, 0.f};

    for (int st = 0; st < NST; ++st) {
        const int slot = st % NSLOT;
        mbar_wait(mbar0 + slot * 8, (unsigned)((st / NSLOT) & 1));
        __syncthreads();                 // all warps done with slot (st-1)%5
        if (st + 4 < NST) issue((st + 4) % NSLOT, st + 4);

        const unsigned sb = dynBase + slot * SLOT_B;
        const unsigned aH = sb + offA;                 // A hh plane
        const unsigned aL = sb + 2560 + offA;          // A hl plane (+32*40*2)
        const unsigned bH = sb + A_BYTES + offB;       // B Wh plane
        const unsigned bL = sb + A_BYTES + 5120 + offB;// B Wl plane (+64*40*2)

#pragma unroll
        for (int kj = 0; kj < 2; ++kj) {  // 2 x k16 per stage
            unsigned Ah[4], Al[4], Bh[4], Bl[4];
            ldm4(Ah, aH + kj * 32);
            ldm4(Al, aL + kj * 32);
            ldm4(Bh, bH + kj * 32);
            ldm4(Bl, bL + kj * 32);
            mma16816(acc0, Ah, Bh);
            mma16816(acc1, Ah, Bh + 2);
            mma16816(acc0, Al, Bh);
            mma16816(acc1, Al, Bh + 2);
            mma16816(acc0, Ah, Bl);
            mma16816(acc1, Ah, Bl + 2);
        }
    }

    // ---- epilogues ----
    const int g = l >> 2, tq = l & 3;
    const int m0 = (wid >> 2) << 4;
    const int n0 = (wid & 3) << 4;

    if (stepMode) {
        // bias + tanh; write tiled bf16 split planes for step t
        __nv_bfloat16* Ht = &g_Hst[t][mtile][0][0][0][0];
#pragma unroll
        for (int half = 0; half < 2; ++half) {
            const int mrow = m0 + g + half * 8;        // local row 0..31
#pragma unroll
            for (int j = 0; j < 2; ++j) {
                const float* acc = j ? acc1 : acc0;
                const int nloc = n0 + j * 8 + 2 * tq;  // 0..63
                const int n = nBase + nloc;
                float v0 = tanhf(acc[2 * half]     + g_beff[n]);
                float v1 = tanhf(acc[2 * half + 1] + g_beff[n + 1]);
                __nv_bfloat16 h0 = __float2bfloat16(v0);
                __nv_bfloat16 h1 = __float2bfloat16(v1);
                __nv_bfloat162 hh; hh.x = h0; hh.y = h1;
                __nv_bfloat162 hl;
                hl.x = __float2bfloat16(v0 - __bfloat162float(h0));
                hl.y = __float2bfloat16(v1 - __bfloat162float(h1));
                const int stage = n >> 5, col = n & 31;
                __nv_bfloat16* base = Ht + stage * 2560 + mrow * APAD + col;
                *(__nv_bfloat162*)base          = hh;  // plane 0
                *(__nv_bfloat162*)(base + 1280) = hl;  // plane 1 (+32*40)
            }
        }
    } else {
        // out[t-1] rows (t-1)*256 + m; bias + fp32 store
#pragma unroll
        for (int half = 0; half < 2; ++half) {
            const int m = mtile * 32 + m0 + g + half * 8;
            float* rowp = out + ((size_t)(t - 1) * 256 + m) * OUTPUT;
#pragma unroll
            for (int j = 0; j < 2; ++j) {
                const float* acc = j ? acc1 : acc0;
                const int n = nBase + n0 + j * 8 + 2 * tq;
                *(float2*)&rowp[n] =
                    make_float2(acc[2 * half]     + bh2o[n],
                                acc[2 * half + 1] + bh2o[n + 1]);
            }
        }
    }
}

// ===========================================================================
// fp32 FFMA2 GEMM for rnn_first (K=128): writes tiled bf16 split planes.
// ===========================================================================
__device__ __forceinline__ unsigned long long pack2(float lo, float hi) {
    unsigned long long r;
    asm("mov.b64 %0, {%1, %2};" : "=l"(r) : "f"(lo), "f"(hi));
    return r;
}
__device__ __forceinline__ void unpack2(unsigned long long v, float& lo, float& hi) {
    asm("mov.b64 {%0, %1}, %2;" : "=f"(lo), "=f"(hi) : "l"(v));
}
__device__ __forceinline__ void ffma2(unsigned long long& d,
                                      unsigned long long a, unsigned long long b) {
    asm("fma.rn.f32x2 %0, %1, %2, %0;" : "+l"(d) : "l"(a), "l"(b));
}

__global__ void rnn_first(const float* __restrict__ x0,
                          const float* __restrict__ Wi2h) {
    __shared__ unsigned long long Asd[2][16][34];
    __shared__ float Bs[2][16][68];

    const int tid = threadIdx.x;
    const int tx = tid & 15, ty = tid >> 4;
    const int rowBase = blockIdx.y * 32;
    const int colBase = blockIdx.x * 64;
    const int am = tid >> 3, ak = (tid & 7) * 2;
    const int bk = tid >> 4, bn = (tid & 15) * 4;

    const float* Aptr = &x0[(size_t)(rowBase + am) * INPUT + ak];
    const float* Bptr = &Wi2h[(size_t)bk * HIDDEN + colBase + bn];

    unsigned long long acc[2][2];
    acc[0][0] = acc[0][1] = acc[1][0] = acc[1][1] = 0ull;

    float2 rA = *(const float2*)Aptr;
    float4 rB = *(const float4*)Bptr;

    const int nT = INPUT >> 4;
    for (int tt = 0; tt < nT; ++tt) {
        const int buf = tt & 1;
        Asd[buf][ak][am]     = pack2(rA.x, rA.x);
        Asd[buf][ak + 1][am] = pack2(rA.y, rA.y);
        *(float4*)&Bs[buf][bk][bn] = rB;
        __syncthreads();
        if (tt + 1 < nT) {
            rA = *(const float2*)(Aptr + (tt + 1) * 16);
            rB = *(const float4*)(Bptr + (size_t)(tt + 1) * 16 * HIDDEN);
        }
#pragma unroll
        for (int kk = 0; kk < 16; ++kk) {
            ulonglong2 ap = *(const ulonglong2*)&Asd[buf][kk][2 * ty];
            ulonglong2 bp = *(const ulonglong2*)&Bs[buf][kk][4 * tx];
            ffma2(acc[0][0], ap.x, bp.x);
            ffma2(acc[0][1], ap.x, bp.y);
            ffma2(acc[1][0], ap.y, bp.x);
            ffma2(acc[1][1], ap.y, bp.y);
        }
    }

    float4 bv = *(const float4*)&g_b1[colBase + 4 * tx];
    float o[2][4];
#pragma unroll
    for (int r = 0; r < 2; ++r) {
        unpack2(acc[r][0], o[r][0], o[r][1]);
        unpack2(acc[r][1], o[r][2], o[r][3]);
        o[r][0] += bv.x; o[r][1] += bv.y; o[r][2] += bv.z; o[r][3] += bv.w;
        const int m = rowBase + 2 * ty + r;
        const int n = colBase + 4 * tx;
#pragma unroll
        for (int c = 0; c < 4; ++c) {
            float v = tanhf(o[r][c]);
            __nv_bfloat16 h = __float2bfloat16(v);
            const int nn = n + c;
            g_Hst[1][m >> 5][nn >> 5][0][m & 31][nn & 31] = h;
            g_Hst[1][m >> 5][nn >> 5][1][m & 31][nn & 31] =
                __float2bfloat16(v - __bfloat162float(h));
        }
    }
}

// ---------------------------- prep kernels ---------------------------------
__global__ void prep_weff(const float* __restrict__ Wh2h,
                          const float* __restrict__ Wh2o,
                          const float* __restrict__ Wi2h) {
    int idx = blockIdx.x * blockDim.x + threadIdx.x;
    int k = idx >> 10, j = idx & 1023;
    float s = Wh2h[idx];
    const float* wo = &Wh2o[k * OUTPUT];
#pragma unroll 8
    for (int i = 0; i < OUTPUT; ++i)
        s += wo[i] * Wi2h[i * HIDDEN + j];
    __nv_bfloat16 wh = __float2bfloat16(s);
    g_BTt[j >> 6][k >> 5][0][j & 63][k & 31] = wh;
    g_BTt[j >> 6][k >> 5][1][j & 63][k & 31] =
        __float2bfloat16(s - __bfloat162float(wh));
}

__global__ void prep_bo(const float* __restrict__ Wh2o) {
    int idx = blockIdx.x * blockDim.x + threadIdx.x;   // HIDDEN*OUTPUT
    int k = idx >> 7, n = idx & 127;
    float w = Wh2o[k * OUTPUT + n];
    __nv_bfloat16 wh = __float2bfloat16(w);
    g_BTot[n >> 6][k >> 5][0][n & 63][k & 31] = wh;
    g_BTot[n >> 6][k >> 5][1][n & 63][k & 31] =
        __float2bfloat16(w - __bfloat162float(wh));
}

__global__ void prep_bias(const float* __restrict__ bi2h,
                          const float* __restrict__ bh2h,
                          const float* __restrict__ bh2o,
                          const float* __restrict__ Wi2h) {
    int j = blockIdx.x * blockDim.x + threadIdx.x;
    if (j >= HIDDEN) return;
    float base = bi2h[j] + bh2h[j];
    g_b1[j] = base;
    float s = base;
#pragma unroll 8
    for (int i = 0; i < OUTPUT; ++i)
        s += bh2o[i] * Wi2h[i * HIDDEN + j];
    g_beff[j] = s;
}

// ---------------------------- launcher -------------------------------------
extern "C" void kernel_launch(void* const* d_in, const int* in_sizes, int n_in,
                              void* d_out, int out_size) {
    const float* x0   = (const float*)d_in[0];
    const float* Wi2h = (const float*)d_in[1];
    const float* bi2h = (const float*)d_in[2];
    const float* Wh2h = (const float*)d_in[3];
    const float* bh2h = (const float*)d_in[4];
    const float* Wh2o = (const float*)d_in[5];
    const float* bh2o = (const float*)d_in[6];
    float* out = (float*)d_out;

    cudaFuncSetAttribute(rnn_fused,
                         cudaFuncAttributeMaxDynamicSharedMemorySize,
                         SM_BYTES);

    prep_weff<<<(HIDDEN * HIDDEN) / 256, 256>>>(Wh2h, Wh2o, Wi2h);
    prep_bo<<<(HIDDEN * OUTPUT) / 256, 256>>>(Wh2o);
    prep_bias<<<(HIDDEN + 255) / 256, 256>>>(bi2h, bh2h, bh2o, Wi2h);
    cudaMemcpyAsync(out, x0, BATCH * OUTPUT * sizeof(float),
                    cudaMemcpyDeviceToDevice, 0);

    rnn_first<<<dim3(HIDDEN / 64, BATCH / 32), 256>>>(x0, Wi2h);

    // steps 2..511: 128 step CTAs + 16 out CTAs (for out[t-1]) per launch
    for (int t = 2; t < TSTEPS; ++t)
        rnn_fused<<<144, 256, SM_BYTES>>>(t, 128, bh2o, out);

    // final: out[511] only (16 CTAs, no step work)
    rnn_fused<<<16, 256, SM_BYTES>>>((int)TSTEPS, 0, bh2o, out);
}

// round 17
// speedup vs baseline: 1.2859x; 1.1003x over previous
#include <cuda_runtime.h>
#include <cuda_bf16.h>
#include <cooperative_groups.h>

namespace cg = cooperative_groups;

#define INPUT   128
#define HIDDEN  1024
#define OUTPUT  128
#define BATCH   256
#define TSTEPS  512

// ---------------------------- device globals -------------------------------
__device__ float g_beff[HIDDEN];
__device__ float g_b1[HIDDEN];
// bf16 split planes of h_t for every t: [t][hh=0/hl=1][m][k]
__device__ __align__(16) __nv_bfloat16 g_Hs[TSTEPS][2][BATCH][HIDDEN];
// bf16 split of W_eff, transposed (n-major): [Wh=0/Wl=1][n][k]
__device__ __align__(16) __nv_bfloat16 g_BT[2][HIDDEN][HIDDEN];
// bf16 split of W_h2o, transposed (n-major): [Wh=0/Wl=1][n][k]
__device__ __align__(16) __nv_bfloat16 g_BTo[2][OUTPUT][HIDDEN];

// ---------------------------- PTX helpers ----------------------------------
__device__ __forceinline__ unsigned smem_u32(const void* p) {
    unsigned a;
    asm("{ .reg .u64 t; cvta.to.shared.u64 t, %1; cvt.u32.u64 %0, t; }"
        : "=r"(a) : "l"(p));
    return a;
}
__device__ __forceinline__ void cp16(unsigned s, const void* g) {
    asm volatile("cp.async.cg.shared.global [%0], [%1], 16;"
                 :: "r"(s), "l"(g) : "memory");
}
__device__ __forceinline__ void cp_commit() {
    asm volatile("cp.async.commit_group;" ::: "memory");
}
__device__ __forceinline__ void ldm4(unsigned* r, unsigned addr) {
    asm volatile("ldmatrix.sync.aligned.m8n8.x4.shared.b16 {%0,%1,%2,%3}, [%4];"
                 : "=r"(r[0]), "=r"(r[1]), "=r"(r[2]), "=r"(r[3]) : "r"(addr));
}
__device__ __forceinline__ void mma16816(float* d, const unsigned* a,
                                         const unsigned* b) {
    asm volatile(
        "mma.sync.aligned.m16n8k16.row.col.f32.bf16.bf16.f32 "
        "{%0,%1,%2,%3}, {%4,%5,%6,%7}, {%8,%9}, {%0,%1,%2,%3};"
        : "+f"(d[0]), "+f"(d[1]), "+f"(d[2]), "+f"(d[3])
        : "r"(a[0]), "r"(a[1]), "r"(a[2]), "r"(a[3]), "r"(b[0]), "r"(b[1]));
}

// ===========================================================================
// Persistent cooperative kernel. 144 CTAs:
//   CTAs [0,128):  h_t = tanh(h_{t-1} @ W_eff + b_eff)    (t = 2..511)
//   CTAs [128,144): out[t-1] = h_{t-1} @ W_h2o + b_h2o    (+ out[511] tail)
// Per iteration: proven R14 pipeline — CTA tile 32x64, warp tile 16x16,
// K=1024, 3-pass bf16 split (hh@Wh + hl@Wh + hh@Wl), BK=32 stages,
// 5 smem slots, 4 stages in flight, one __syncthreads per stage.
// Persistence extra: next iteration's B (weights, step-invariant) prefetch
// issues BEFORE grid.sync(), overlapping the barrier with L2 weight fetch.
// smem 75KB: AH/AL[5][32][40], BH/BL[5][64][40] bf16.
// ===========================================================================
#define S_APAD   40
#define S_ASLOT  (32 * S_APAD)              // 1280 elems
#define S_BSLOT  (64 * S_APAD)              // 2560 elems
#define S_AH     0
#define S_AL     (5 * S_ASLOT)              // 6400
#define S_BH     (10 * S_ASLOT)             // 12800
#define S_BL     (S_BH + 5 * S_BSLOT)       // 25600
#define S_TOT_E  (S_BH + 10 * S_BSLOT)      // 38400 elems = 76800 B
#define SM_BYTES (S_TOT_E * 2)
#define S_NST    32                          // k32 stages

__global__ void __launch_bounds__(256, 1)
rnn_persist(const float* __restrict__ bh2o, float* __restrict__ out) {
    extern __shared__ __align__(16) __nv_bfloat16 dyn[];
    cg::grid_group grid = cg::this_grid();

    const int tid = threadIdx.x, wid = tid >> 5, l = tid & 31;
    const bool stepMode = blockIdx.x < 128;
    const int bx = stepMode ? blockIdx.x : blockIdx.x - 128;

    int nBase, mBase;
    const __nv_bfloat16 *gBh, *gBl;
    if (stepMode) {
        nBase = (bx & 15) * 64;  mBase = (bx >> 4) * 32;
        gBh = &g_BT[0][nBase][0];  gBl = &g_BT[1][nBase][0];
    } else {
        nBase = (bx & 1) * 64;   mBase = (bx >> 1) * 32;
        gBh = &g_BTo[0][nBase][0]; gBl = &g_BTo[1][nBase][0];
    }
    const __nv_bfloat16 *gAh = nullptr, *gAl = nullptr;   // set per iteration

    auto load_B = [&](int slot, int st) {
        const int k0 = st * 32;
#pragma unroll
        for (int i = 0; i < 2; ++i) {   // B: 2 parts x 64 rows x 4 segs = 512
            int c = tid + i * 256;
            int part = c >> 8, r = (c & 255) >> 2, s = (c & 3) * 8;
            __nv_bfloat16* d = dyn + (part ? S_BL : S_BH) + slot * S_BSLOT
                               + r * S_APAD + s;
            cp16(smem_u32(d), (part ? gBl : gBh) + r * HIDDEN + k0 + s);
        }
    };
    auto load_A = [&](int slot, int st) {
        const int k0 = st * 32;
        int c = tid;                    // A: 2 parts x 32 rows x 4 segs = 256
        int part = c >> 7, r = (c & 127) >> 2, s = (c & 3) * 8;
        __nv_bfloat16* d = dyn + (part ? S_AL : S_AH) + slot * S_ASLOT
                           + r * S_APAD + s;
        cp16(smem_u32(d), (part ? gAl : gAh) + r * HIDDEN + k0 + s);
    };

    // ldmatrix lane offsets (bytes within a slot)
    const int rowA = ((wid >> 2) << 4) + (l & 15);
    const unsigned offA = (unsigned)(rowA * S_APAD + ((l >> 4) << 3)) * 2;
    const int rowB = ((wid & 3) << 4) + (l & 7) + ((l >> 4) << 3);
    const unsigned offB = (unsigned)(rowB * S_APAD + (((l >> 3) & 1) << 3)) * 2;
    const unsigned uAh = smem_u32(dyn + S_AH) + offA;
    const unsigned uAl = smem_u32(dyn + S_AL) + offA;
    const unsigned uBh = smem_u32(dyn + S_BH) + offB;
    const unsigned uBl = smem_u32(dyn + S_BL) + offB;

    const int g = l >> 2, tq = l & 3;
    const int m0 = (wid >> 2) << 4;
    const int n0 = (wid & 3) << 4;

    // one GEMM iteration (A ptrs set; B stages 0..3 already ISSUED, uncommitted)
    auto gemm_iter = [&](float* acc0, float* acc1) {
        load_A(0, 0); cp_commit();      // group0 = B(0..3) + A(0)
        load_A(1, 1); cp_commit();
        load_A(2, 2); cp_commit();
        load_A(3, 3); cp_commit();
        for (int st = 0; st < S_NST; ++st) {
            asm volatile("cp.async.wait_group 3;" ::: "memory");
            __syncthreads();            // stage st ready; slot (st-1)%5 free
            if (st + 4 < S_NST) { load_B((st + 4) % 5, st + 4);
                                  load_A((st + 4) % 5, st + 4); }
            cp_commit();
            const int slot = st % 5;
            const unsigned aH = uAh + (unsigned)(slot * S_ASLOT) * 2;
            const unsigned aL = uAl + (unsigned)(slot * S_ASLOT) * 2;
            const unsigned bH = uBh + (unsigned)(slot * S_BSLOT) * 2;
            const unsigned bL = uBl + (unsigned)(slot * S_BSLOT) * 2;
#pragma unroll
            for (int kj = 0; kj < 2; ++kj) {
                unsigned Ah[4], Al[4], Bh[4], Bl[4];
                ldm4(Ah, aH + kj * 32);
                ldm4(Al, aL + kj * 32);
                ldm4(Bh, bH + kj * 32);
                ldm4(Bl, bL + kj * 32);
                mma16816(acc0, Ah, Bh);
                mma16816(acc1, Ah, Bh + 2);
                mma16816(acc0, Al, Bh);
                mma16816(acc1, Al, Bh + 2);
                mma16816(acc0, Ah, Bl);
                mma16816(acc1, Ah, Bl + 2);
            }
        }
        asm volatile("cp.async.wait_group 0;" ::: "memory");
        __syncthreads();                // all warps done with smem slots
    };

    // prefetch B for the first iteration (t = 2)
    load_B(0, 0); load_B(1, 1); load_B(2, 2); load_B(3, 3);

    for (int t = 2; t < TSTEPS; ++t) {
        gAh = &g_Hs[t - 1][0][mBase][0];
        gAl = &g_Hs[t - 1][1][mBase][0];

        float acc0[4] = {0.f, 0.f, 0.f, 0.f};
        float acc1[4] = {0.f, 0.f, 0.f, 0.f};
        gemm_iter(acc0, acc1);

        // prefetch next iteration's B (step-invariant) before the barrier;
        // skip when this CTA has no further iteration (clean exit).
        if (t + 1 < TSTEPS || !stepMode) {
            load_B(0, 0); load_B(1, 1); load_B(2, 2); load_B(3, 3);
        }

        if (stepMode) {
            // bias + tanh; write bf16 split planes for step t
#pragma unroll
            for (int half = 0; half < 2; ++half) {
                const int m = mBase + m0 + g + half * 8;
#pragma unroll
                for (int j = 0; j < 2; ++j) {
                    const float* acc = j ? acc1 : acc0;
                    const int n = nBase + n0 + j * 8 + 2 * tq;
                    float v0 = tanhf(acc[2 * half]     + g_beff[n]);
                    float v1 = tanhf(acc[2 * half + 1] + g_beff[n + 1]);
                    __nv_bfloat16 h0 = __float2bfloat16(v0);
                    __nv_bfloat16 h1 = __float2bfloat16(v1);
                    __nv_bfloat162 hh; hh.x = h0; hh.y = h1;
                    __nv_bfloat162 hl;
                    hl.x = __float2bfloat16(v0 - __bfloat162float(h0));
                    hl.y = __float2bfloat16(v1 - __bfloat162float(h1));
                    *(__nv_bfloat162*)&g_Hs[t][0][m][n] = hh;
                    *(__nv_bfloat162*)&g_Hs[t][1][m][n] = hl;
                }
            }
        } else {
            // out[t-1] rows (t-1)*256 + m
#pragma unroll
            for (int half = 0; half < 2; ++half) {
                const int m = mBase + m0 + g + half * 8;
                float* rowp = out + ((size_t)(t - 1) * 256 + m) * OUTPUT;
#pragma unroll
                for (int j = 0; j < 2; ++j) {
                    const float* acc = j ? acc1 : acc0;
                    const int n = nBase + n0 + j * 8 + 2 * tq;
                    *(float2*)&rowp[n] =
                        make_float2(acc[2 * half]     + bh2o[n],
                                    acc[2 * half + 1] + bh2o[n + 1]);
                }
            }
        }

        __threadfence();
        grid.sync();
    }

    // tail: out[511] on the 16 out CTAs (B already prefetched above)
    if (!stepMode) {
        gAh = &g_Hs[TSTEPS - 1][0][mBase][0];
        gAl = &g_Hs[TSTEPS - 1][1][mBase][0];
        float acc0[4] = {0.f, 0.f, 0.f, 0.f};
        float acc1[4] = {0.f, 0.f, 0.f, 0.f};
        gemm_iter(acc0, acc1);
#pragma unroll
        for (int half = 0; half < 2; ++half) {
            const int m = mBase + m0 + g + half * 8;
            float* rowp = out + ((size_t)(TSTEPS - 1) * 256 + m) * OUTPUT;
#pragma unroll
            for (int j = 0; j < 2; ++j) {
                const float* acc = j ? acc1 : acc0;
                const int n = nBase + n0 + j * 8 + 2 * tq;
                *(float2*)&rowp[n] =
                    make_float2(acc[2 * half]     + bh2o[n],
                                acc[2 * half + 1] + bh2o[n + 1]);
            }
        }
    }
}

// ===========================================================================
// fp32 FFMA2 GEMM for rnn_first (K=128): writes bf16 split planes directly.
// ===========================================================================
__device__ __forceinline__ unsigned long long pack2(float lo, float hi) {
    unsigned long long r;
    asm("mov.b64 %0, {%1, %2};" : "=l"(r) : "f"(lo), "f"(hi));
    return r;
}
__device__ __forceinline__ void unpack2(unsigned long long v, float& lo, float& hi) {
    asm("mov.b64 {%0, %1}, %2;" : "=f"(lo), "=f"(hi) : "l"(v));
}
__device__ __forceinline__ void ffma2(unsigned long long& d,
                                      unsigned long long a, unsigned long long b) {
    asm("fma.rn.f32x2 %0, %1, %2, %0;" : "+l"(d) : "l"(a), "l"(b));
}

__global__ void rnn_first(const float* __restrict__ x0,
                          const float* __restrict__ Wi2h) {
    __shared__ unsigned long long Asd[2][16][34];
    __shared__ float Bs[2][16][68];

    const int tid = threadIdx.x;
    const int tx = tid & 15, ty = tid >> 4;
    const int rowBase = blockIdx.y * 32;
    const int colBase = blockIdx.x * 64;
    const int am = tid >> 3, ak = (tid & 7) * 2;
    const int bk = tid >> 4, bn = (tid & 15) * 4;

    const float* Aptr = &x0[(size_t)(rowBase + am) * INPUT + ak];
    const float* Bptr = &Wi2h[(size_t)bk * HIDDEN + colBase + bn];

    unsigned long long acc[2][2];
    acc[0][0] = acc[0][1] = acc[1][0] = acc[1][1] = 0ull;

    float2 rA = *(const float2*)Aptr;
    float4 rB = *(const float4*)Bptr;

    const int nT = INPUT >> 4;
    for (int tt = 0; tt < nT; ++tt) {
        const int buf = tt & 1;
        Asd[buf][ak][am]     = pack2(rA.x, rA.x);
        Asd[buf][ak + 1][am] = pack2(rA.y, rA.y);
        *(float4*)&Bs[buf][bk][bn] = rB;
        __syncthreads();
        if (tt + 1 < nT) {
            rA = *(const float2*)(Aptr + (tt + 1) * 16);
            rB = *(const float4*)(Bptr + (size_t)(tt + 1) * 16 * HIDDEN);
        }
#pragma unroll
        for (int kk = 0; kk < 16; ++kk) {
            ulonglong2 ap = *(const ulonglong2*)&Asd[buf][kk][2 * ty];
            ulonglong2 bp = *(const ulonglong2*)&Bs[buf][kk][4 * tx];
            ffma2(acc[0][0], ap.x, bp.x);
            ffma2(acc[0][1], ap.x, bp.y);
            ffma2(acc[1][0], ap.y, bp.x);
            ffma2(acc[1][1], ap.y, bp.y);
        }
    }

    float4 bv = *(const float4*)&g_b1[colBase + 4 * tx];
    float o[2][4];
#pragma unroll
    for (int r = 0; r < 2; ++r) {
        unpack2(acc[r][0], o[r][0], o[r][1]);
        unpack2(acc[r][1], o[r][2], o[r][3]);
        o[r][0] += bv.x; o[r][1] += bv.y; o[r][2] += bv.z; o[r][3] += bv.w;
        const int m = rowBase + 2 * ty + r;
        const int n = colBase + 4 * tx;
#pragma unroll
        for (int c = 0; c < 4; ++c) {
            float v = tanhf(o[r][c]);
            __nv_bfloat16 h = __float2bfloat16(v);
            g_Hs[1][0][m][n + c] = h;
            g_Hs[1][1][m][n + c] = __float2bfloat16(v - __bfloat162float(h));
        }
    }
}

// ---------------------------- prep kernels ---------------------------------
__global__ void prep_weff(const float* __restrict__ Wh2h,
                          const float* __restrict__ Wh2o,
                          const float* __restrict__ Wi2h) {
    int idx = blockIdx.x * blockDim.x + threadIdx.x;
    int k = idx >> 10, j = idx & 1023;
    float s = Wh2h[idx];
    const float* wo = &Wh2o[k * OUTPUT];
#pragma unroll 8
    for (int i = 0; i < OUTPUT; ++i)
        s += wo[i] * Wi2h[i * HIDDEN + j];
    __nv_bfloat16 wh = __float2bfloat16(s);
    g_BT[0][j][k] = wh;
    g_BT[1][j][k] = __float2bfloat16(s - __bfloat162float(wh));
}

__global__ void prep_bo(const float* __restrict__ Wh2o) {
    int idx = blockIdx.x * blockDim.x + threadIdx.x;   // HIDDEN*OUTPUT
    int k = idx >> 7, n = idx & 127;
    float w = Wh2o[k * OUTPUT + n];
    __nv_bfloat16 wh = __float2bfloat16(w);
    g_BTo[0][n][k] = wh;
    g_BTo[1][n][k] = __float2bfloat16(w - __bfloat162float(wh));
}

__global__ void prep_bias(const float* __restrict__ bi2h,
                          const float* __restrict__ bh2h,
                          const float* __restrict__ bh2o,
                          const float* __restrict__ Wi2h) {
    int j = blockIdx.x * blockDim.x + threadIdx.x;
    if (j >= HIDDEN) return;
    float base = bi2h[j] + bh2h[j];
    g_b1[j] = base;
    float s = base;
#pragma unroll 8
    for (int i = 0; i < OUTPUT; ++i)
        s += bh2o[i] * Wi2h[i * HIDDEN + j];
    g_beff[j] = s;
}

// ---------------------------- launcher -------------------------------------
extern "C" void kernel_launch(void* const* d_in, const int* in_sizes, int n_in,
                              void* d_out, int out_size) {
    const float* x0   = (const float*)d_in[0];
    const float* Wi2h = (const float*)d_in[1];
    const float* bi2h = (const float*)d_in[2];
    const float* Wh2h = (const float*)d_in[3];
    const float* bh2h = (const float*)d_in[4];
    const float* Wh2o = (const float*)d_in[5];
    const float* bh2o = (const float*)d_in[6];
    float* out = (float*)d_out;

    cudaFuncSetAttribute(rnn_persist,
                         cudaFuncAttributeMaxDynamicSharedMemorySize,
                         SM_BYTES);

    prep_weff<<<(HIDDEN * HIDDEN) / 256, 256>>>(Wh2h, Wh2o, Wi2h);
    prep_bo<<<(HIDDEN * OUTPUT) / 256, 256>>>(Wh2o);
    prep_bias<<<(HIDDEN + 255) / 256, 256>>>(bi2h, bh2h, bh2o, Wi2h);
    cudaMemcpyAsync(out, x0, BATCH * OUTPUT * sizeof(float),
                    cudaMemcpyDeviceToDevice, 0);

    rnn_first<<<dim3(HIDDEN / 64, BATCH / 32), 256>>>(x0, Wi2h);

    // one cooperative persistent launch for steps 2..511 + all outputs
    const float* bh2o_arg = bh2o;
    float* out_arg = out;
    void* kargs[] = { (void*)&bh2o_arg, (void*)&out_arg };
    cudaLaunchCooperativeKernel((const void*)rnn_persist,
                                dim3(144, 1, 1), dim3(256, 1, 1),
                                kargs, (size_t)SM_BYTES, (cudaStream_t)0);
}